// round 17
// baseline (speedup 1.0000x reference)
#include <cuda_runtime.h>
#include <cuda_bf16.h>
#include <cstdint>
#include <cstddef>

// ---------------- problem dims ----------------
static constexpr int Mdim = 8192;   // B*T
static constexpr int Ndim = 1024;   // codebook rows
static constexpr int Kdim = 512;    // D

// ------- tiling: 64x128 CTA, TWO warps of 64x64, 4 barrier domains/SM -----
static constexpr int MT = 64;
static constexpr int NT = 128;
static constexpr int KC = 64;            // K elems per chunk
static constexpr int NCHUNK = Kdim / KC; // 8
static constexpr int THREADS = 64;       // 2 warps, each 64(M) x 64(N)
static constexpr int A_CHUNK_BYTES = 64 * 128;    // 8 KB
static constexpr int B_CHUNK_BYTES = 128 * 128;   // 16 KB
static constexpr int STAGE_BYTES = A_CHUNK_BYTES + B_CHUNK_BYTES; // 24576
static constexpr int SM_MBAR = 2 * STAGE_BYTES;   // 49152
static constexpr int SM_TOTAL = SM_MBAR + 64;     // 49216 -> 4 CTAs/SM

__device__ float g_xsq[Mdim];
__device__ float g_csq[Ndim];
// chunk-blocked, PRE-SWIZZLED bf16 images (identical layout to R16)
__device__ __align__(16) uint8_t g_xb[(size_t)(Mdim / 64) * NCHUNK * A_CHUNK_BYTES];  // 8 MB
__device__ __align__(16) uint8_t g_cb[(size_t)(Ndim / 128) * NCHUNK * B_CHUNK_BYTES]; // 1 MB

// ---------------- helpers ----------------
__device__ __forceinline__ uint32_t smem_u32(const void* p) {
    uint32_t a;
    asm("{ .reg .u64 t; cvta.to.shared.u64 t, %1; cvt.u32.u64 %0, t; }"
        : "=r"(a) : "l"(p));
    return a;
}
#define SW128(o) ((o) ^ (((o) >> 3) & 0x70))

__device__ __forceinline__ uint32_t pack_bf16x2(float a, float b) {
    uint32_t r;
    asm("cvt.rn.bf16x2.f32 %0, %1, %2;" : "=r"(r) : "f"(b), "f"(a));
    return r;
}
__device__ __forceinline__ void ldsm_x4(uint32_t* r, uint32_t addr) {
    asm volatile("ldmatrix.sync.aligned.m8n8.x4.shared.b16 {%0,%1,%2,%3}, [%4];"
                 : "=r"(r[0]), "=r"(r[1]), "=r"(r[2]), "=r"(r[3]) : "r"(addr));
}
__device__ __forceinline__ void mma_bf16(float* c, const uint32_t* a,
                                         uint32_t b0, uint32_t b1) {
    asm volatile(
        "mma.sync.aligned.m16n8k16.row.col.f32.bf16.bf16.f32 "
        "{%0,%1,%2,%3}, {%4,%5,%6,%7}, {%8,%9}, {%0,%1,%2,%3};"
        : "+f"(c[0]), "+f"(c[1]), "+f"(c[2]), "+f"(c[3])
        : "r"(a[0]), "r"(a[1]), "r"(a[2]), "r"(a[3]), "r"(b0), "r"(b1));
}

#define MBAR_INIT(a, cnt) \
    asm volatile("mbarrier.init.shared.b64 [%0], %1;" :: "r"(a), "r"(cnt) : "memory")
#define MBAR_EXPECT_TX(a, bytes) \
    asm volatile("mbarrier.arrive.expect_tx.shared.b64 _, [%0], %1;" \
                 :: "r"(a), "r"(bytes) : "memory")
#define MBAR_WAIT(addr, ph) do {                                                    \
    asm volatile(                                                                   \
        "{\n\t.reg .pred P;\n"                                                      \
        "MW_%=:\n\t"                                                                \
        "mbarrier.try_wait.parity.acquire.cta.shared::cta.b64 P, [%0], %1, 0x989680;\n\t" \
        "@P bra.uni MD_%=;\n\t"                                                     \
        "bra.uni MW_%=;\n"                                                          \
        "MD_%=:\n\t}"                                                               \
        :: "r"(addr), "r"(ph) : "memory");                                          \
} while (0)

__device__ __forceinline__ void bulk_copy(uint32_t dst_smem, const void* src,
                                          uint32_t bytes, uint32_t mbar) {
    asm volatile(
        "cp.async.bulk.shared::cluster.global.mbarrier::complete_tx::bytes "
        "[%0], [%1], %2, [%3];"
        :: "r"(dst_smem), "l"(src), "r"(bytes), "r"(mbar) : "memory");
}

// ------- prep: fp32 -> bf16 into chunk-blocked PRE-SWIZZLED layout + norms --
__global__ void __launch_bounds__(256) prep_kernel(const float* __restrict__ x,
                                                   const float* __restrict__ cb) {
    int row  = blockIdx.x * 8 + (threadIdx.x >> 5);
    int lane = threadIdx.x & 31;
    const float4* src;
    uint8_t* dstbase;
    float* dsts;
    int rloc, cbytes;
    if (row < Mdim) {
        src = reinterpret_cast<const float4*>(x) + (size_t)row * (Kdim / 4);
        dstbase = g_xb + (size_t)(row >> 6) * NCHUNK * A_CHUNK_BYTES;
        rloc = row & 63;  cbytes = A_CHUNK_BYTES;
        dsts = g_xsq + row;
    } else if (row < Mdim + Ndim) {
        int r = row - Mdim;
        src = reinterpret_cast<const float4*>(cb) + (size_t)r * (Kdim / 4);
        dstbase = g_cb + (size_t)(r >> 7) * NCHUNK * B_CHUNK_BYTES;
        rloc = r & 127;  cbytes = B_CHUNK_BYTES;
        dsts = g_csq + r;
    } else return;
    float s = 0.f;
    #pragma unroll
    for (int t = 0; t < Kdim / 128; t++) {
        int j = lane + t * 32;
        float4 v = src[j];
        s += v.x * v.x + v.y * v.y + v.z * v.z + v.w * v.w;
        uint2 pk;
        pk.x = pack_bf16x2(v.x, v.y);
        pk.y = pack_bf16x2(v.z, v.w);
        const int c = j >> 4;
        const uint32_t off = SW128((uint32_t)(rloc * 128 + (j & 15) * 8));
        *reinterpret_cast<uint2*>(dstbase + (size_t)c * cbytes + off) = pk;
    }
    #pragma unroll
    for (int o = 16; o; o >>= 1) s += __shfl_xor_sync(0xffffffffu, s, o);
    if (lane == 0) *dsts = s;
}

// ---------------- GEMM: 2 warps x (64x64), TMA-bulk fed stages ------------
__global__ void __launch_bounds__(THREADS, 4)
gemm_kernel(const float* __restrict__ precision, float* __restrict__ out) {
    extern __shared__ char smem[];
    const uint32_t sb = smem_u32(smem);
    const int tid  = threadIdx.x;
    const int lane = tid & 31;
    const int wn   = tid >> 5;        // 0..1: 64-col slab
    const int m0 = blockIdx.y * MT;
    const int n0 = blockIdx.x * NT;
    const uint8_t* srcA = g_xb + (size_t)blockIdx.y * NCHUNK * A_CHUNK_BYTES;
    const uint8_t* srcB = g_cb + (size_t)blockIdx.x * NCHUNK * B_CHUNK_BYTES;

    // ldmatrix per-thread offsets (bytes within 128B-row tiles, pre-swizzle)
    const int aRow0 = lane & 15;                 // + mf*16, mf = 0..3
    const int aColB = ((lane >> 4) & 1) * 16;
    const int bRow0 = wn * 64 + (lane & 7) + ((lane >> 4) & 1) * 8;
    const int bColB = ((lane >> 3) & 1) * 16;

    float acc[4][8][4];
    #pragma unroll
    for (int mf = 0; mf < 4; mf++)
        #pragma unroll
        for (int nf = 0; nf < 8; nf++)
            #pragma unroll
            for (int q = 0; q < 4; q++) acc[mf][nf][q] = 0.f;

    if (tid == 0) {
        MBAR_INIT(sb + SM_MBAR + 0, 1);
        MBAR_INIT(sb + SM_MBAR + 8, 1);
    }
    asm volatile("fence.proxy.async.shared::cta;" ::: "memory");
    __syncthreads();

    if (tid == 0) {
        MBAR_EXPECT_TX(sb + SM_MBAR + 0, (uint32_t)STAGE_BYTES);
        bulk_copy(sb, srcA, A_CHUNK_BYTES, sb + SM_MBAR + 0);
        bulk_copy(sb + A_CHUNK_BYTES, srcB, B_CHUNK_BYTES, sb + SM_MBAR + 0);
    }

    #pragma unroll 1
    for (int c = 0; c < NCHUNK; c++) {
        if (c >= 1) __syncthreads();   // both warps done reading chunk c-1
        if (c + 1 < NCHUNK && tid == 0) {
            const int s2 = (c + 1) & 1;
            MBAR_EXPECT_TX(sb + SM_MBAR + 8 * s2, (uint32_t)STAGE_BYTES);
            bulk_copy(sb + s2 * STAGE_BYTES,
                      srcA + (size_t)(c + 1) * A_CHUNK_BYTES,
                      A_CHUNK_BYTES, sb + SM_MBAR + 8 * s2);
            bulk_copy(sb + s2 * STAGE_BYTES + A_CHUNK_BYTES,
                      srcB + (size_t)(c + 1) * B_CHUNK_BYTES,
                      B_CHUNK_BYTES, sb + SM_MBAR + 8 * s2);
        }
        MBAR_WAIT(sb + SM_MBAR + 8 * (c & 1), (c >> 1) & 1);

        const uint32_t sA = sb + (c & 1) * STAGE_BYTES;
        const uint32_t sB = sA + A_CHUNK_BYTES;

        #pragma unroll
        for (int ks = 0; ks < 4; ks++) {
            uint32_t af[4][4];
            #pragma unroll
            for (int mf = 0; mf < 4; mf++)
                ldsm_x4(af[mf], sA + SW128((uint32_t)((aRow0 + mf * 16) * 128
                                                      + ks * 32 + aColB)));
            uint32_t bf[4][4];
            #pragma unroll
            for (int nf2 = 0; nf2 < 4; nf2++)
                ldsm_x4(bf[nf2], sB + SW128((uint32_t)((bRow0 + nf2 * 16) * 128
                                                       + ks * 32 + bColB)));
            #pragma unroll
            for (int mf = 0; mf < 4; mf++)
                #pragma unroll
                for (int nf = 0; nf < 8; nf++)
                    mma_bf16(acc[mf][nf], af[mf],
                             bf[nf >> 1][(nf & 1) * 2],
                             bf[nf >> 1][(nf & 1) * 2 + 1]);
        }
    }
    __syncthreads();   // stage smem free before epilogue reuse

    // ---------------- epilogue ----------------
    float* sE = reinterpret_cast<float*>(smem);   // [64][132] = 33.8 KB
    const int erow = lane >> 2;                   // + mf*16 (+8)
    const int ecol = wn * 64 + (lane & 3) * 2;
    #pragma unroll
    for (int mf = 0; mf < 4; mf++) {
        #pragma unroll
        for (int nf = 0; nf < 8; nf++) {
            float2* p0 = reinterpret_cast<float2*>(
                &sE[(erow + mf * 16) * 132 + ecol + nf * 8]);
            float2* p1 = reinterpret_cast<float2*>(
                &sE[(erow + mf * 16 + 8) * 132 + ecol + nf * 8]);
            *p0 = make_float2(acc[mf][nf][0], acc[mf][nf][1]);
            *p1 = make_float2(acc[mf][nf][2], acc[mf][nf][3]);
        }
    }
    __syncthreads();

    const float prec = precision[0];
    const int cj = (tid & 31) * 4;              // col group of 4 (128 cols)
    const float4 cs = *reinterpret_cast<const float4*>(&g_csq[n0 + cj]);
    #pragma unroll 4
    for (int it = 0; it < 32; it++) {
        const int r = (tid >> 5) + it * 2;      // 0..63
        const float xs = g_xsq[m0 + r];
        const float* sp = &sE[r * 132 + cj];
        float4 v;
        v.x = prec * (2.f * sp[0] - xs - cs.x);
        v.y = prec * (2.f * sp[1] - xs - cs.y);
        v.z = prec * (2.f * sp[2] - xs - cs.z);
        v.w = prec * (2.f * sp[3] - xs - cs.w);
        *reinterpret_cast<float4*>(&out[(size_t)(m0 + r) * Ndim + n0 + cj]) = v;
    }
}

// ---------------- launch ----------------
extern "C" void kernel_launch(void* const* d_in, const int* in_sizes, int n_in,
                              void* d_out, int out_size) {
    (void)in_sizes; (void)n_in; (void)out_size;
    const float* x    = (const float*)d_in[0];
    const float* cb   = (const float*)d_in[1];
    const float* prec = (const float*)d_in[2];
    float* out = (float*)d_out;

    cudaFuncSetAttribute(gemm_kernel,
                         cudaFuncAttributeMaxDynamicSharedMemorySize, SM_TOTAL);

    prep_kernel<<<(Mdim + Ndim) / 8, 256>>>(x, cb);
    dim3 grid(Ndim / NT, Mdim / MT);   // (8, 128) = 1024 CTAs
    gemm_kernel<<<grid, THREADS, SM_TOTAL>>>(prec, out);
}